// round 2
// baseline (speedup 1.0000x reference)
#include <cuda_runtime.h>

#define NNODES 50000
#define NEDGES 400000
#define PAD 68
#define INV_SQRT3 0.57735026918962576451f

__device__ float g_x[(size_t)NNODES * 256];
__device__ float g_wt[49664];

#define WT_MLP1 0
#define WT_MLP2 512
#define WT_MLP3 4608
#define WT_MLP4 8704
#define WT_L0A  25088
#define WT_L0B  29184
#define WT_L1A  33280
#define WT_L1B  37376
#define WT_UP0  41472
#define WT_UP1  45568

__global__ void prep_kernel(const float* __restrict__ w1, const float* __restrict__ w2,
                            const float* __restrict__ w3, const float* __restrict__ w4,
                            const float* __restrict__ l0, const float* __restrict__ l1,
                            const float* __restrict__ up0, const float* __restrict__ up1) {
  int t = blockIdx.x * blockDim.x + threadIdx.x;
  if (t >= 49664) return;
  float v;
  if (t < 512)        { int u = t;        int n = u >> 3, k = u & 7;  v = w1[k*64 + n]; }
  else if (t < 4608)  { int u = t-512;    int n = u >> 6, k = u & 63; v = w2[k*64 + n]; }
  else if (t < 8704)  { int u = t-4608;   int n = u >> 6, k = u & 63; v = w3[k*64 + n]; }
  else if (t < 25088) { int u = t-8704;   int q = u >> 12; int r = u & 4095;
                        int n = r >> 6, k = r & 63;        v = w4[k*256 + q*64 + n]; }
  else if (t < 29184) { int u = t-25088;  int n = u >> 6, k = u & 63; v = l0[k*64 + n]; }
  else if (t < 33280) { int u = t-29184;  int n = u >> 6, k = u & 63; v = l0[(64+k)*64 + n]; }
  else if (t < 37376) { int u = t-33280;  int n = u >> 6, k = u & 63; v = l1[k*64 + n]; }
  else if (t < 41472) { int u = t-37376;  int n = u >> 6, k = u & 63; v = l1[(64+k)*64 + n]; }
  else if (t < 45568) { int u = t-41472;  int n = u >> 6, k = u & 63; v = up0[k*64 + n]; }
  else                { int u = t-45568;  int n = u >> 6, k = u & 63; v = up1[k*64 + n]; }
  g_wt[t] = v;
}

template<int K, int LDA>
__device__ __forceinline__ void gemm4x4(const float* __restrict__ A, const float* __restrict__ B,
                                        float acc[4][4], int ty, int tx) {
#pragma unroll
  for (int kk = 0; kk < K; kk += 4) {
    float4 a[4], b[4];
#pragma unroll
    for (int i = 0; i < 4; i++) a[i] = *(const float4*)(A + (ty*4 + i)*LDA + kk);
#pragma unroll
    for (int j = 0; j < 4; j++) b[j] = *(const float4*)(B + (tx + 16*j)*PAD + kk);
#pragma unroll
    for (int i = 0; i < 4; i++)
#pragma unroll
      for (int j = 0; j < 4; j++) {
        float s = acc[i][j];
        s = fmaf(a[i].x, b[j].x, s);
        s = fmaf(a[i].y, b[j].y, s);
        s = fmaf(a[i].z, b[j].z, s);
        s = fmaf(a[i].w, b[j].w, s);
        acc[i][j] = s;
      }
  }
}

__device__ __forceinline__ void zero4x4(float a[4][4]) {
#pragma unroll
  for (int i = 0; i < 4; i++)
#pragma unroll
    for (int j = 0; j < 4; j++) a[i][j] = 0.f;
}

__device__ __forceinline__ float silu_f(float x) { return x * (1.f / (1.f + __expf(-x))); }

__device__ __forceinline__ void load_w64(float* dst, const float* __restrict__ src, int tid) {
  for (int f = tid; f < 1024; f += 256) {
    int r = f >> 4, c = f & 15;
    *(float4*)(dst + r*PAD + c*4) = *(const float4*)(src + r*64 + c*4);
  }
}

__global__ __launch_bounds__(256) void node_kernel(const float* __restrict__ nf) {
  extern __shared__ float sm[];
  float* NF = sm;                  // 64 x 256
  float* Wt = sm + 16384;          // 64 x PAD
  float* Ab = sm + 16384 + 4352;   // 64 x PAD
  int tid = threadIdx.x, ty = tid >> 4, tx = tid & 15;
  int n0 = blockIdx.x * 64;

  for (int f = tid; f < 4096; f += 256) {
    int r = f >> 6, c4 = f & 63;
    if (n0 + r < NNODES)
      *(float4*)(NF + r*256 + c4*4) = *(const float4*)(nf + (size_t)(n0 + r)*256 + c4*4);
  }
  __syncthreads();

  for (int p = 0; p < 4; p++) {
    load_w64(Wt, g_wt + (p == 0 ? WT_UP0 : WT_UP1), tid);
    for (int f = tid; f < 4096; f += 256) {
      int r = f >> 6, c = f & 63;
      Ab[r*PAD + c] = (p == 0) ? NF[r*256 + c] : NF[r*256 + 64 + c*3 + (p - 1)];
    }
    __syncthreads();
    float fr[4][4]; zero4x4(fr);
    gemm4x4<64, PAD>(Ab, Wt, fr, ty, tx);
#pragma unroll
    for (int i = 0; i < 4; i++) {
      int r = ty*4 + i;
      if (n0 + r < NNODES) {
#pragma unroll
        for (int j = 0; j < 4; j++)
          g_x[(size_t)(n0 + r)*256 + p*64 + tx + 16*j] = fr[i][j];
      }
    }
    __syncthreads();
  }
}

__global__ __launch_bounds__(256) void edge_kernel(const float* __restrict__ ea,
                                                   const float* __restrict__ ef,
                                                   const int* __restrict__ eidx,
                                                   float* __restrict__ out) {
  extern __shared__ float sm[];
  float* A0  = sm;             // 64 x PAD  (H1/H3 ; dead in epilogue)
  float* A1  = sm + 4352;      // 64 x PAD  (H2, then dot)
  float* Tb  = sm + 8704;      // 64 x PAD
  float* S0  = sm + 13056;     // 64 x PAD
  float* Wa  = sm + 17408;     // 64 x PAD
  float* Wb  = sm + 21760;     // 64 x PAD
  float* S1  = sm + 26112;     // 3 x (64 x PAD)
  float* F   = sm + 39168;     // 64 x 8
  float* a0s = sm + 39680;     // 64
  float* a1s = sm + 39744;     // 64 x 3
  int*   idxs = (int*)(sm + 39936);  // 64
  // epilogue OUT[64][256] aliases sm[0 .. 16384)

  int tid = threadIdx.x, ty = tid >> 4, tx = tid & 15;
  int e0 = blockIdx.x * 64;

  if (tid < 64) {
    idxs[tid] = eidx[e0 + tid];
    float4 av = *(const float4*)(ea + (size_t)(e0 + tid)*4);
    a0s[tid] = av.x;
    a1s[tid*3 + 0] = av.y; a1s[tid*3 + 1] = av.z; a1s[tid*3 + 2] = av.w;
  }
  if (tid < 128)
    *(float4*)(F + tid*4) = *(const float4*)(ef + (size_t)e0*8 + tid*4);
  __syncthreads();

  // gather s0 + three s1 planes (coalesced float4; overlaps MLP latency)
  for (int f = tid; f < 4096; f += 256) {
    int e = f >> 6, c4 = f & 63;
    float4 v = *(const float4*)(g_x + (size_t)idxs[e]*256 + c4*4);
    if (c4 < 16) *(float4*)(S0 + e*PAD + c4*4) = v;
    else {
      int m = (c4 - 16) >> 4, cc = (c4 - 16) & 15;
      *(float4*)(S1 + m*4352 + e*PAD + cc*4) = v;
    }
  }

  float fr[4][4];

  // MLP stage 1 (K=8)
  for (int f = tid; f < 128; f += 256) {
    int r = f >> 1, c = f & 1;
    *(float4*)(Wa + r*PAD + c*4) = *(const float4*)(g_wt + WT_MLP1 + r*8 + c*4);
  }
  __syncthreads();
  zero4x4(fr);
  gemm4x4<8, 8>(F, Wa, fr, ty, tx);
#pragma unroll
  for (int i = 0; i < 4; i++) { int e = ty*4 + i;
#pragma unroll
    for (int j = 0; j < 4; j++) A0[e*PAD + tx + 16*j] = silu_f(fr[i][j]); }
  __syncthreads();

  // MLP stage 2
  load_w64(Wa, g_wt + WT_MLP2, tid);
  __syncthreads();
  zero4x4(fr);
  gemm4x4<64, PAD>(A0, Wa, fr, ty, tx);
  __syncthreads();
#pragma unroll
  for (int i = 0; i < 4; i++) { int e = ty*4 + i;
#pragma unroll
    for (int j = 0; j < 4; j++) A1[e*PAD + tx + 16*j] = silu_f(fr[i][j]); }
  __syncthreads();

  // MLP stage 3 -> A0 = H3
  load_w64(Wa, g_wt + WT_MLP3, tid);
  __syncthreads();
  zero4x4(fr);
  gemm4x4<64, PAD>(A1, Wa, fr, ty, tx);
  __syncthreads();
#pragma unroll
  for (int i = 0; i < 4; i++) { int e = ty*4 + i;
#pragma unroll
    for (int j = 0; j < 4; j++) A0[e*PAD + tx + 16*j] = silu_f(fr[i][j]); }

  // dot[e][c] = sum_m s1_m a1_m / sqrt(3)  -> A1 (A1 free after sync below)
  __syncthreads();
  for (int f = tid; f < 4096; f += 256) {
    int e = f >> 6, c = f & 63;
    float d = S1[0*4352 + e*PAD + c]*a1s[e*3 + 0]
            + S1[1*4352 + e*PAD + c]*a1s[e*3 + 1]
            + S1[2*4352 + e*PAD + c]*a1s[e*3 + 2];
    A1[e*PAD + c] = d * INV_SQRT3;
  }

  float U[4][4], Y[4][4];

  // q=1 : U = (w2 ∘ s0) @ L1A
  load_w64(Wa, g_wt + WT_MLP4 + 1*4096, tid);
  __syncthreads();
  zero4x4(fr);
  gemm4x4<64, PAD>(A0, Wa, fr, ty, tx);
#pragma unroll
  for (int i = 0; i < 4; i++) { int e = ty*4 + i;
#pragma unroll
    for (int j = 0; j < 4; j++) { int c = tx + 16*j; Tb[e*PAD + c] = fr[i][j]*S0[e*PAD + c]; } }
  load_w64(Wb, g_wt + WT_L1A, tid);
  __syncthreads();
  zero4x4(U);
  gemm4x4<64, PAD>(Tb, Wb, U, ty, tx);
  __syncthreads();

  // q=0 : Y = (w1 ∘ s0 ∘ a0) @ L0A
  load_w64(Wa, g_wt + WT_MLP4 + 0*4096, tid);
  __syncthreads();
  zero4x4(fr);
  gemm4x4<64, PAD>(A0, Wa, fr, ty, tx);
#pragma unroll
  for (int i = 0; i < 4; i++) { int e = ty*4 + i; float az = a0s[e];
#pragma unroll
    for (int j = 0; j < 4; j++) { int c = tx + 16*j; Tb[e*PAD + c] = fr[i][j]*S0[e*PAD + c]*az; } }
  load_w64(Wb, g_wt + WT_L0A, tid);
  __syncthreads();
  zero4x4(Y);
  gemm4x4<64, PAD>(Tb, Wb, Y, ty, tx);
  __syncthreads();

  // q=3 : Y += (w4 ∘ dot) @ L0B
  load_w64(Wa, g_wt + WT_MLP4 + 3*4096, tid);
  __syncthreads();
  zero4x4(fr);
  gemm4x4<64, PAD>(A0, Wa, fr, ty, tx);
#pragma unroll
  for (int i = 0; i < 4; i++) { int e = ty*4 + i;
#pragma unroll
    for (int j = 0; j < 4; j++) { int c = tx + 16*j; Tb[e*PAD + c] = fr[i][j]*A1[e*PAD + c]; } }
  load_w64(Wb, g_wt + WT_L0B, tid);
  __syncthreads();
  gemm4x4<64, PAD>(Tb, Wb, Y, ty, tx);
  __syncthreads();

  // q=2 : S1_m *= w3 in place; V_m = S1_m @ L1B; epilogue
  load_w64(Wa, g_wt + WT_MLP4 + 2*4096, tid);
  __syncthreads();
  zero4x4(fr);
  gemm4x4<64, PAD>(A0, Wa, fr, ty, tx);
#pragma unroll
  for (int i = 0; i < 4; i++) { int e = ty*4 + i;
#pragma unroll
    for (int j = 0; j < 4; j++) { int c = tx + 16*j; float w = fr[i][j];
      S1[0*4352 + e*PAD + c] *= w;
      S1[1*4352 + e*PAD + c] *= w;
      S1[2*4352 + e*PAD + c] *= w; } }
  load_w64(Wb, g_wt + WT_L1B, tid);
  __syncthreads();
  // A0/A1/Tb/S0 dead -> sm[0..16384) = OUT[64][256]
#pragma unroll
  for (int i = 0; i < 4; i++) { int e = ty*4 + i;
#pragma unroll
    for (int j = 0; j < 4; j++) sm[e*256 + tx + 16*j] = Y[i][j]; }
#pragma unroll
  for (int m = 0; m < 3; m++) {
    zero4x4(fr);
    gemm4x4<64, PAD>(S1 + m*4352, Wb, fr, ty, tx);
#pragma unroll
    for (int i = 0; i < 4; i++) { int e = ty*4 + i; float am = a1s[e*3 + m]; float az = a0s[e];
#pragma unroll
      for (int j = 0; j < 4; j++) { int d = tx + 16*j;
        sm[e*256 + 64 + d*3 + m] = am*U[i][j] + az*fr[i][j]; } }
  }
  __syncthreads();
  float* og = out + (size_t)e0*256;
  for (int f = tid; f < 4096; f += 256)
    *(float4*)(og + f*4) = *(const float4*)(sm + f*4);
}

extern "C" void kernel_launch(void* const* d_in, const int* in_sizes, int n_in,
                              void* d_out, int out_size) {
  (void)in_sizes; (void)n_in; (void)out_size;
  const float* nf  = (const float*)d_in[0];
  const float* ea  = (const float*)d_in[1];
  const float* ef  = (const float*)d_in[2];
  const float* up0 = (const float*)d_in[3];
  const float* up1 = (const float*)d_in[4];
  const float* w1  = (const float*)d_in[5];
  const float* w2  = (const float*)d_in[6];
  const float* w3  = (const float*)d_in[7];
  const float* w4  = (const float*)d_in[8];
  const float* l0  = (const float*)d_in[9];
  const float* l1  = (const float*)d_in[10];
  const int*  eidx = (const int*)d_in[11];
  float* out = (float*)d_out;

  cudaFuncSetAttribute(node_kernel, cudaFuncAttributeMaxDynamicSharedMemorySize, 100352);
  cudaFuncSetAttribute(edge_kernel, cudaFuncAttributeMaxDynamicSharedMemorySize, 160000);

  prep_kernel<<<(49664 + 255) / 256, 256>>>(w1, w2, w3, w4, l0, l1, up0, up1);
  node_kernel<<<(NNODES + 63) / 64, 256, 100352>>>(nf);
  edge_kernel<<<NEDGES / 64, 256, 160000>>>(ea, ef, eidx, out);
}

// round 4
// speedup vs baseline: 1.5928x; 1.5928x over previous
#include <cuda_runtime.h>

#define NNODES 50000
#define NEDGES 400000
#define PAD 68
#define INV_SQRT3 0.57735026918962576451f

__device__ float g_x[(size_t)NNODES * 256];
__device__ float g_tp[(size_t)4 * NEDGES * 64];
__device__ float g_wt[49664];

#define WT_MLP1 0
#define WT_MLP2 512
#define WT_MLP3 4608
#define WT_MLP4 8704
#define WT_L0A  25088
#define WT_L0B  29184
#define WT_L1A  33280
#define WT_L1B  37376
#define WT_UP0  41472
#define WT_UP1  45568

__global__ void prep_kernel(const float* __restrict__ w1, const float* __restrict__ w2,
                            const float* __restrict__ w3, const float* __restrict__ w4,
                            const float* __restrict__ l0, const float* __restrict__ l1,
                            const float* __restrict__ up0, const float* __restrict__ up1) {
  int t = blockIdx.x * blockDim.x + threadIdx.x;
  if (t >= 49664) return;
  float v;
  if (t < 512)        { int u = t;        int n = u >> 3, k = u & 7;  v = w1[k*64 + n]; }
  else if (t < 4608)  { int u = t-512;    int n = u >> 6, k = u & 63; v = w2[k*64 + n]; }
  else if (t < 8704)  { int u = t-4608;   int n = u >> 6, k = u & 63; v = w3[k*64 + n]; }
  else if (t < 25088) { int u = t-8704;   int q = u >> 12; int r = u & 4095;
                        int n = r >> 6, k = r & 63;        v = w4[k*256 + q*64 + n]; }
  else if (t < 29184) { int u = t-25088;  int n = u >> 6, k = u & 63; v = l0[k*64 + n]; }
  else if (t < 33280) { int u = t-29184;  int n = u >> 6, k = u & 63; v = l0[(64+k)*64 + n]; }
  else if (t < 37376) { int u = t-33280;  int n = u >> 6, k = u & 63; v = l1[k*64 + n]; }
  else if (t < 41472) { int u = t-37376;  int n = u >> 6, k = u & 63; v = l1[(64+k)*64 + n]; }
  else if (t < 45568) { int u = t-41472;  int n = u >> 6, k = u & 63; v = up0[k*64 + n]; }
  else                { int u = t-45568;  int n = u >> 6, k = u & 63; v = up1[k*64 + n]; }
  g_wt[t] = v;
}

template<int K, int LDA>
__device__ __forceinline__ void gemm4x4(const float* __restrict__ A, const float* __restrict__ B,
                                        float acc[4][4], int ty, int tx) {
#pragma unroll
  for (int kk = 0; kk < K; kk += 4) {
    float4 a[4], b[4];
#pragma unroll
    for (int i = 0; i < 4; i++) a[i] = *(const float4*)(A + (ty*4 + i)*LDA + kk);
#pragma unroll
    for (int j = 0; j < 4; j++) b[j] = *(const float4*)(B + (tx + 16*j)*PAD + kk);
#pragma unroll
    for (int i = 0; i < 4; i++)
#pragma unroll
      for (int j = 0; j < 4; j++) {
        float s = acc[i][j];
        s = fmaf(a[i].x, b[j].x, s);
        s = fmaf(a[i].y, b[j].y, s);
        s = fmaf(a[i].z, b[j].z, s);
        s = fmaf(a[i].w, b[j].w, s);
        acc[i][j] = s;
      }
  }
}

// 2 rows x 4 cols fragment, A stride PAD, B stride PAD
template<int K>
__device__ __forceinline__ void gemm2x4(const float* __restrict__ A, const float* __restrict__ B,
                                        float acc[2][4], int ty, int tx) {
#pragma unroll
  for (int kk = 0; kk < K; kk += 4) {
    float4 a[2], b[4];
#pragma unroll
    for (int i = 0; i < 2; i++) a[i] = *(const float4*)(A + (ty*2 + i)*PAD + kk);
#pragma unroll
    for (int j = 0; j < 4; j++) b[j] = *(const float4*)(B + (tx + 16*j)*PAD + kk);
#pragma unroll
    for (int i = 0; i < 2; i++)
#pragma unroll
      for (int j = 0; j < 4; j++) {
        float s = acc[i][j];
        s = fmaf(a[i].x, b[j].x, s);
        s = fmaf(a[i].y, b[j].y, s);
        s = fmaf(a[i].z, b[j].z, s);
        s = fmaf(a[i].w, b[j].w, s);
        acc[i][j] = s;
      }
  }
}

__device__ __forceinline__ void zero4x4(float a[4][4]) {
#pragma unroll
  for (int i = 0; i < 4; i++)
#pragma unroll
    for (int j = 0; j < 4; j++) a[i][j] = 0.f;
}

__device__ __forceinline__ float silu_f(float x) { return x * (1.f / (1.f + __expf(-x))); }

__device__ __forceinline__ void load_w64(float* dst, const float* __restrict__ src, int tid) {
  for (int f = tid; f < 1024; f += 256) {
    int r = f >> 4, c = f & 15;
    *(float4*)(dst + r*PAD + c*4) = *(const float4*)(src + r*64 + c*4);
  }
}

// ---------------- node up-projection ----------------
__global__ __launch_bounds__(256) void node_kernel(const float* __restrict__ nf) {
  extern __shared__ float sm[];
  float* NF = sm;                  // 64 x 256
  float* Wt = sm + 16384;          // 64 x PAD
  float* Ab = sm + 16384 + 4352;   // 64 x PAD
  int tid = threadIdx.x, ty = tid >> 4, tx = tid & 15;
  int n0 = blockIdx.x * 64;

  for (int f = tid; f < 4096; f += 256) {
    int r = f >> 6, c4 = f & 63;
    if (n0 + r < NNODES)
      *(float4*)(NF + r*256 + c4*4) = *(const float4*)(nf + (size_t)(n0 + r)*256 + c4*4);
  }
  __syncthreads();

  for (int p = 0; p < 4; p++) {
    load_w64(Wt, g_wt + (p == 0 ? WT_UP0 : WT_UP1), tid);
    for (int f = tid; f < 4096; f += 256) {
      int r = f >> 6, c = f & 63;
      Ab[r*PAD + c] = (p == 0) ? NF[r*256 + c] : NF[r*256 + 64 + c*3 + (p - 1)];
    }
    __syncthreads();
    float fr[4][4]; zero4x4(fr);
    gemm4x4<64, PAD>(Ab, Wt, fr, ty, tx);
#pragma unroll
    for (int i = 0; i < 4; i++) {
      int r = ty*4 + i;
      if (n0 + r < NNODES) {
#pragma unroll
        for (int j = 0; j < 4; j++)
          g_x[(size_t)(n0 + r)*256 + p*64 + tx + 16*j] = fr[i][j];
      }
    }
    __syncthreads();
  }
}

// ---------------- per-edge MLP -> g_tp (q-major) ----------------
__global__ __launch_bounds__(256) void mlp_kernel(const float* __restrict__ ef) {
  extern __shared__ float sm[];
  float* F  = sm;          // 64 x 8
  float* Wa = sm + 512;    // 64 x PAD
  float* A0 = sm + 4864;   // 64 x PAD
  float* A1 = sm + 9216;   // 64 x PAD   (total 13568 floats)
  int tid = threadIdx.x, ty = tid >> 4, tx = tid & 15;
  int e0 = blockIdx.x * 64;

  if (tid < 128)
    *(float4*)(F + tid*4) = *(const float4*)(ef + (size_t)e0*8 + tid*4);
  for (int f = tid; f < 128; f += 256) {
    int r = f >> 1, c = f & 1;
    *(float4*)(Wa + r*PAD + c*4) = *(const float4*)(g_wt + WT_MLP1 + r*8 + c*4);
  }
  __syncthreads();

  float fr[4][4];
  zero4x4(fr);
  gemm4x4<8, 8>(F, Wa, fr, ty, tx);
  __syncthreads();
#pragma unroll
  for (int i = 0; i < 4; i++) { int e = ty*4 + i;
#pragma unroll
    for (int j = 0; j < 4; j++) A0[e*PAD + tx + 16*j] = silu_f(fr[i][j]); }
  load_w64(Wa, g_wt + WT_MLP2, tid);
  __syncthreads();

  zero4x4(fr);
  gemm4x4<64, PAD>(A0, Wa, fr, ty, tx);
  __syncthreads();
#pragma unroll
  for (int i = 0; i < 4; i++) { int e = ty*4 + i;
#pragma unroll
    for (int j = 0; j < 4; j++) A1[e*PAD + tx + 16*j] = silu_f(fr[i][j]); }
  load_w64(Wa, g_wt + WT_MLP3, tid);
  __syncthreads();

  zero4x4(fr);
  gemm4x4<64, PAD>(A1, Wa, fr, ty, tx);
  __syncthreads();
#pragma unroll
  for (int i = 0; i < 4; i++) { int e = ty*4 + i;
#pragma unroll
    for (int j = 0; j < 4; j++) A0[e*PAD + tx + 16*j] = silu_f(fr[i][j]); }
  __syncthreads();

#pragma unroll
  for (int q = 0; q < 4; q++) {
    load_w64(Wa, g_wt + WT_MLP4 + q*4096, tid);
    __syncthreads();
    zero4x4(fr);
    gemm4x4<64, PAD>(A0, Wa, fr, ty, tx);
    float* og = g_tp + (size_t)q * NEDGES * 64 + (size_t)e0 * 64;
#pragma unroll
    for (int i = 0; i < 4; i++) { int e = ty*4 + i;
#pragma unroll
      for (int j = 0; j < 4; j++) og[e*64 + tx + 16*j] = fr[i][j]; }
    __syncthreads();
  }
}

// ---------------- tensor-product + final linears ----------------
__global__ __launch_bounds__(256, 2) void edge2_kernel(const float* __restrict__ ea,
                                                       const int* __restrict__ eidx,
                                                       float* __restrict__ out) {
  extern __shared__ float sm[];
  float* S0  = sm;             // 32 x PAD (2176)
  float* S1  = sm + 2176;      // 3 x 2176
  float* Tb  = sm + 8704;      // 2176
  float* Wb  = sm + 10880;     // 64 x PAD (4352)
  float* a0s = sm + 15232;     // 32
  float* a1s = sm + 15264;     // 96
  int*  idxs = (int*)(sm + 15360); // 32
  // epilogue OUT[32][256] = 8192 floats aliases sm[0..8192) (S0+S1 dead)

  int tid = threadIdx.x, ty = tid >> 4, tx = tid & 15;
  int e0 = blockIdx.x * 32;

  if (tid < 32) {
    idxs[tid] = eidx[e0 + tid];
    float4 av = *(const float4*)(ea + (size_t)(e0 + tid)*4);
    a0s[tid] = av.x;
    a1s[tid*3 + 0] = av.y; a1s[tid*3 + 1] = av.z; a1s[tid*3 + 2] = av.w;
  }
  __syncthreads();

  // gather s0 + s1 planes; load first weight tile concurrently
  for (int f = tid; f < 2048; f += 256) {
    int e = f >> 6, c4 = f & 63;
    float4 v = *(const float4*)(g_x + (size_t)idxs[e]*256 + c4*4);
    if (c4 < 16) *(float4*)(S0 + e*PAD + c4*4) = v;
    else {
      int m = (c4 - 16) >> 4, cc = (c4 - 16) & 15;
      *(float4*)(S1 + m*2176 + e*PAD + cc*4) = v;
    }
  }
  load_w64(Wb, g_wt + WT_L0A, tid);
  __syncthreads();

  const float* tp0 = g_tp + (size_t)e0 * 64;
  const size_t QS = (size_t)NEDGES * 64;

  float Y[2][4], U[2][4], V[3][2][4];

  // q=0 : Tb = w1 ∘ S0 ∘ a0 ; Y = Tb @ L0A
  for (int f = tid; f < 512; f += 256) {
    int e = f >> 4, c4 = f & 15;
    float4 w = *(const float4*)(tp0 + e*64 + c4*4);
    float4 s = *(const float4*)(S0 + e*PAD + c4*4);
    float az = a0s[e];
    float4 r; r.x = w.x*s.x*az; r.y = w.y*s.y*az; r.z = w.z*s.z*az; r.w = w.w*s.w*az;
    *(float4*)(Tb + e*PAD + c4*4) = r;
  }
  __syncthreads();
#pragma unroll
  for (int i = 0; i < 2; i++)
#pragma unroll
    for (int j = 0; j < 4; j++) Y[i][j] = 0.f;
  gemm2x4<64>(Tb, Wb, Y, ty, tx);
  __syncthreads();

  // q=3 : Tb = w4 ∘ dot(S1,a1)/sqrt3 ; Y += Tb @ L0B
  load_w64(Wb, g_wt + WT_L0B, tid);
  for (int f = tid; f < 512; f += 256) {
    int e = f >> 4, c4 = f & 15;
    float4 w = *(const float4*)(tp0 + 3*QS + e*64 + c4*4);
    float4 s0m = *(const float4*)(S1 + 0*2176 + e*PAD + c4*4);
    float4 s1m = *(const float4*)(S1 + 1*2176 + e*PAD + c4*4);
    float4 s2m = *(const float4*)(S1 + 2*2176 + e*PAD + c4*4);
    float a1x = a1s[e*3+0], a1y = a1s[e*3+1], a1z = a1s[e*3+2];
    float4 r;
    r.x = w.x * (s0m.x*a1x + s1m.x*a1y + s2m.x*a1z) * INV_SQRT3;
    r.y = w.y * (s0m.y*a1x + s1m.y*a1y + s2m.y*a1z) * INV_SQRT3;
    r.z = w.z * (s0m.z*a1x + s1m.z*a1y + s2m.z*a1z) * INV_SQRT3;
    r.w = w.w * (s0m.w*a1x + s1m.w*a1y + s2m.w*a1z) * INV_SQRT3;
    *(float4*)(Tb + e*PAD + c4*4) = r;
  }
  __syncthreads();
  gemm2x4<64>(Tb, Wb, Y, ty, tx);
  __syncthreads();

  // q=1 : Tb = w2 ∘ S0 ; U = Tb @ L1A
  load_w64(Wb, g_wt + WT_L1A, tid);
  for (int f = tid; f < 512; f += 256) {
    int e = f >> 4, c4 = f & 15;
    float4 w = *(const float4*)(tp0 + 1*QS + e*64 + c4*4);
    float4 s = *(const float4*)(S0 + e*PAD + c4*4);
    float4 r; r.x = w.x*s.x; r.y = w.y*s.y; r.z = w.z*s.z; r.w = w.w*s.w;
    *(float4*)(Tb + e*PAD + c4*4) = r;
  }
  __syncthreads();
#pragma unroll
  for (int i = 0; i < 2; i++)
#pragma unroll
    for (int j = 0; j < 4; j++) U[i][j] = 0.f;
  gemm2x4<64>(Tb, Wb, U, ty, tx);
  __syncthreads();

  // q=2, m=0..2 : Tb = w3 ∘ S1_m ; V_m = Tb @ L1B
  load_w64(Wb, g_wt + WT_L1B, tid);
#pragma unroll
  for (int m = 0; m < 3; m++) {
    for (int f = tid; f < 512; f += 256) {
      int e = f >> 4, c4 = f & 15;
      float4 w = *(const float4*)(tp0 + 2*QS + e*64 + c4*4);
      float4 s = *(const float4*)(S1 + m*2176 + e*PAD + c4*4);
      float4 r; r.x = w.x*s.x; r.y = w.y*s.y; r.z = w.z*s.z; r.w = w.w*s.w;
      *(float4*)(Tb + e*PAD + c4*4) = r;
    }
    __syncthreads();
#pragma unroll
    for (int i = 0; i < 2; i++)
#pragma unroll
      for (int j = 0; j < 4; j++) V[m][i][j] = 0.f;
    gemm2x4<64>(Tb, Wb, V[m], ty, tx);
    __syncthreads();
  }

  // epilogue: OUT aliases sm[0..8192) — S0/S1 are dead, Tb/Wb untouched
#pragma unroll
  for (int i = 0; i < 2; i++) {
    int e = ty*2 + i;
    float az = a0s[e];
    float am0 = a1s[e*3+0], am1 = a1s[e*3+1], am2 = a1s[e*3+2];
#pragma unroll
    for (int j = 0; j < 4; j++) {
      int d = tx + 16*j;
      sm[e*256 + d] = Y[i][j];
      sm[e*256 + 64 + d*3 + 0] = am0*U[i][j] + az*V[0][i][j];
      sm[e*256 + 64 + d*3 + 1] = am1*U[i][j] + az*V[1][i][j];
      sm[e*256 + 64 + d*3 + 2] = am2*U[i][j] + az*V[2][i][j];
    }
  }
  __syncthreads();
  float* og = out + (size_t)e0 * 256;
  for (int f = tid; f < 2048; f += 256)
    *(float4*)(og + f*4) = *(const float4*)(sm + f*4);
}

extern "C" void kernel_launch(void* const* d_in, const int* in_sizes, int n_in,
                              void* d_out, int out_size) {
  (void)in_sizes; (void)n_in; (void)out_size;
  const float* nf  = (const float*)d_in[0];
  const float* ea  = (const float*)d_in[1];
  const float* ef  = (const float*)d_in[2];
  const float* up0 = (const float*)d_in[3];
  const float* up1 = (const float*)d_in[4];
  const float* w1  = (const float*)d_in[5];
  const float* w2  = (const float*)d_in[6];
  const float* w3  = (const float*)d_in[7];
  const float* w4  = (const float*)d_in[8];
  const float* l0  = (const float*)d_in[9];
  const float* l1  = (const float*)d_in[10];
  const int*  eidx = (const int*)d_in[11];
  float* out = (float*)d_out;

  cudaFuncSetAttribute(node_kernel, cudaFuncAttributeMaxDynamicSharedMemorySize, 100352);
  cudaFuncSetAttribute(mlp_kernel,  cudaFuncAttributeMaxDynamicSharedMemorySize, 54272);
  cudaFuncSetAttribute(edge2_kernel, cudaFuncAttributeMaxDynamicSharedMemorySize, 61696);

  prep_kernel<<<(49664 + 255) / 256, 256>>>(w1, w2, w3, w4, l0, l1, up0, up1);
  node_kernel<<<(NNODES + 63) / 64, 256, 100352>>>(nf);
  mlp_kernel<<<NEDGES / 64, 256, 54272>>>(ef);
  edge2_kernel<<<NEDGES / 32, 256, 61696>>>(ea, eidx, out);
}

// round 5
// speedup vs baseline: 1.6829x; 1.0566x over previous
#include <cuda_runtime.h>

#define NNODES 50000
#define NEDGES 400000
#define PAD 68
#define INV_SQRT3 0.57735026918962576451f

__device__ float g_x[(size_t)NNODES * 256];
__device__ float g_tp[(size_t)4 * NEDGES * 64];
__device__ float g_wt[49664];

#define WT_MLP1 0
#define WT_MLP2 512
#define WT_MLP3 4608
#define WT_MLP4 8704
#define WT_L0A  25088
#define WT_L0B  29184
#define WT_L1A  33280
#define WT_L1B  37376
#define WT_UP0  41472
#define WT_UP1  45568

__global__ void prep_kernel(const float* __restrict__ w1, const float* __restrict__ w2,
                            const float* __restrict__ w3, const float* __restrict__ w4,
                            const float* __restrict__ l0, const float* __restrict__ l1,
                            const float* __restrict__ up0, const float* __restrict__ up1) {
  int t = blockIdx.x * blockDim.x + threadIdx.x;
  if (t >= 49664) return;
  float v;
  if (t < 512)        { int u = t;        int n = u >> 3, k = u & 7;  v = w1[k*64 + n]; }
  else if (t < 4608)  { int u = t-512;    int n = u >> 6, k = u & 63; v = w2[k*64 + n]; }
  else if (t < 8704)  { int u = t-4608;   int n = u >> 6, k = u & 63; v = w3[k*64 + n]; }
  else if (t < 25088) { int u = t-8704;   int q = u >> 12; int r = u & 4095;
                        int n = r >> 6, k = r & 63;        v = w4[k*256 + q*64 + n]; }
  else if (t < 29184) { int u = t-25088;  int n = u >> 6, k = u & 63; v = l0[k*64 + n]; }
  else if (t < 33280) { int u = t-29184;  int n = u >> 6, k = u & 63; v = l0[(64+k)*64 + n]; }
  else if (t < 37376) { int u = t-33280;  int n = u >> 6, k = u & 63; v = l1[k*64 + n]; }
  else if (t < 41472) { int u = t-37376;  int n = u >> 6, k = u & 63; v = l1[(64+k)*64 + n]; }
  else if (t < 45568) { int u = t-41472;  int n = u >> 6, k = u & 63; v = up0[k*64 + n]; }
  else                { int u = t-45568;  int n = u >> 6, k = u & 63; v = up1[k*64 + n]; }
  g_wt[t] = v;
}

// 4 rows x 4 cols; rows = ty*4+i, cols = tx+16j; A stride LDA, B stride PAD
template<int K, int LDA>
__device__ __forceinline__ void gemm4x4(const float* __restrict__ A, const float* __restrict__ B,
                                        float acc[4][4], int ty, int tx) {
#pragma unroll
  for (int kk = 0; kk < K; kk += 4) {
    float4 b[4];
#pragma unroll
    for (int j = 0; j < 4; j++) b[j] = *(const float4*)(B + (tx + 16*j)*PAD + kk);
#pragma unroll
    for (int i = 0; i < 4; i++) {
      float4 a = *(const float4*)(A + (ty*4 + i)*LDA + kk);
#pragma unroll
      for (int j = 0; j < 4; j++) {
        float s = acc[i][j];
        s = fmaf(a.x, b[j].x, s);
        s = fmaf(a.y, b[j].y, s);
        s = fmaf(a.z, b[j].z, s);
        s = fmaf(a.w, b[j].w, s);
        acc[i][j] = s;
      }
    }
  }
}

// 8 rows x 4 cols; rows = ty*8+i
template<int K, int LDA>
__device__ __forceinline__ void gemm8x4(const float* __restrict__ A, const float* __restrict__ B,
                                        float acc[8][4], int ty, int tx) {
#pragma unroll
  for (int kk = 0; kk < K; kk += 4) {
    float4 b[4];
#pragma unroll
    for (int j = 0; j < 4; j++) b[j] = *(const float4*)(B + (tx + 16*j)*PAD + kk);
#pragma unroll
    for (int i = 0; i < 8; i++) {
      float4 a = *(const float4*)(A + (ty*8 + i)*LDA + kk);
#pragma unroll
      for (int j = 0; j < 4; j++) {
        float s = acc[i][j];
        s = fmaf(a.x, b[j].x, s);
        s = fmaf(a.y, b[j].y, s);
        s = fmaf(a.z, b[j].z, s);
        s = fmaf(a.w, b[j].w, s);
        acc[i][j] = s;
      }
    }
  }
}

__device__ __forceinline__ float silu_f(float x) { return x * (1.f / (1.f + __expf(-x))); }

__device__ __forceinline__ void load_w64(float* dst, const float* __restrict__ src, int tid) {
  for (int f = tid; f < 1024; f += 256) {
    int r = f >> 4, c = f & 15;
    *(float4*)(dst + r*PAD + c*4) = *(const float4*)(src + r*64 + c*4);
  }
}

// ---------------- node up-projection ----------------
__global__ __launch_bounds__(256) void node_kernel(const float* __restrict__ nf) {
  extern __shared__ float sm[];
  float* NF = sm;                  // 64 x 256
  float* Wt = sm + 16384;          // 64 x PAD
  float* Ab = sm + 16384 + 4352;   // 64 x PAD
  int tid = threadIdx.x, ty = tid >> 4, tx = tid & 15;
  int n0 = blockIdx.x * 64;

  for (int f = tid; f < 4096; f += 256) {
    int r = f >> 6, c4 = f & 63;
    if (n0 + r < NNODES)
      *(float4*)(NF + r*256 + c4*4) = *(const float4*)(nf + (size_t)(n0 + r)*256 + c4*4);
  }
  __syncthreads();

  for (int p = 0; p < 4; p++) {
    load_w64(Wt, g_wt + (p == 0 ? WT_UP0 : WT_UP1), tid);
    for (int f = tid; f < 4096; f += 256) {
      int r = f >> 6, c = f & 63;
      Ab[r*PAD + c] = (p == 0) ? NF[r*256 + c] : NF[r*256 + 64 + c*3 + (p - 1)];
    }
    __syncthreads();
    float fr[4][4];
#pragma unroll
    for (int i = 0; i < 4; i++)
#pragma unroll
      for (int j = 0; j < 4; j++) fr[i][j] = 0.f;
    gemm4x4<64, PAD>(Ab, Wt, fr, ty, tx);
#pragma unroll
    for (int i = 0; i < 4; i++) {
      int r = ty*4 + i;
      if (n0 + r < NNODES) {
#pragma unroll
        for (int j = 0; j < 4; j++)
          g_x[(size_t)(n0 + r)*256 + p*64 + tx + 16*j] = fr[i][j];
      }
    }
    __syncthreads();
  }
}

// ---------------- per-edge MLP -> g_tp (q-major), 128-edge tiles ----------------
__global__ __launch_bounds__(256, 2) void mlp_kernel(const float* __restrict__ ef) {
  extern __shared__ float sm[];
  float* F  = sm;           // 128 x 8   (1024)
  float* Wa = sm + 1024;    // 64 x PAD  (4352)
  float* A0 = sm + 5376;    // 128 x PAD (8704)
  float* A1 = sm + 14080;   // 128 x PAD (8704)  -> total 22784 floats
  int tid = threadIdx.x, ty = tid >> 4, tx = tid & 15;
  int e0 = blockIdx.x * 128;

  *(float4*)(F + tid*4) = *(const float4*)(ef + (size_t)e0*8 + tid*4);
  for (int f = tid; f < 128; f += 256) {
    int r = f >> 1, c = f & 1;
    *(float4*)(Wa + r*PAD + c*4) = *(const float4*)(g_wt + WT_MLP1 + r*8 + c*4);
  }
  __syncthreads();

  float fr[8][4];
#pragma unroll
  for (int i = 0; i < 8; i++)
#pragma unroll
    for (int j = 0; j < 4; j++) fr[i][j] = 0.f;
  gemm8x4<8, 8>(F, Wa, fr, ty, tx);
  __syncthreads();
#pragma unroll
  for (int i = 0; i < 8; i++) { int e = ty*8 + i;
#pragma unroll
    for (int j = 0; j < 4; j++) A0[e*PAD + tx + 16*j] = silu_f(fr[i][j]); }
  load_w64(Wa, g_wt + WT_MLP2, tid);
  __syncthreads();

#pragma unroll
  for (int i = 0; i < 8; i++)
#pragma unroll
    for (int j = 0; j < 4; j++) fr[i][j] = 0.f;
  gemm8x4<64, PAD>(A0, Wa, fr, ty, tx);
  __syncthreads();
#pragma unroll
  for (int i = 0; i < 8; i++) { int e = ty*8 + i;
#pragma unroll
    for (int j = 0; j < 4; j++) A1[e*PAD + tx + 16*j] = silu_f(fr[i][j]); }
  load_w64(Wa, g_wt + WT_MLP3, tid);
  __syncthreads();

#pragma unroll
  for (int i = 0; i < 8; i++)
#pragma unroll
    for (int j = 0; j < 4; j++) fr[i][j] = 0.f;
  gemm8x4<64, PAD>(A1, Wa, fr, ty, tx);
  __syncthreads();
#pragma unroll
  for (int i = 0; i < 8; i++) { int e = ty*8 + i;
#pragma unroll
    for (int j = 0; j < 4; j++) A0[e*PAD + tx + 16*j] = silu_f(fr[i][j]); }
  __syncthreads();

#pragma unroll
  for (int q = 0; q < 4; q++) {
    load_w64(Wa, g_wt + WT_MLP4 + q*4096, tid);
    __syncthreads();
#pragma unroll
    for (int i = 0; i < 8; i++)
#pragma unroll
      for (int j = 0; j < 4; j++) fr[i][j] = 0.f;
    gemm8x4<64, PAD>(A0, Wa, fr, ty, tx);
    float* og = g_tp + (size_t)q * NEDGES * 64 + (size_t)e0 * 64;
#pragma unroll
    for (int i = 0; i < 8; i++) { int e = ty*8 + i;
#pragma unroll
      for (int j = 0; j < 4; j++) og[e*64 + tx + 16*j] = fr[i][j]; }
    __syncthreads();
  }
}

// ---------------- tensor-product + final linears, 64-edge tiles ----------------
__global__ __launch_bounds__(256, 2) void edge2_kernel(const float* __restrict__ ea,
                                                       const int* __restrict__ eidx,
                                                       float* __restrict__ out) {
  extern __shared__ float sm[];
  float* S0  = sm;              // 4352   (later holds y0)
  float* S1  = sm + 4352;       // 3 x 4352 (later holds y1 planes)
  float* Tb  = sm + 17408;      // 4352
  float* Wb  = sm + 21760;      // 4352
  float* a0s = sm + 26112;      // 64
  float* a1s = sm + 26176;      // 192
  int*  idxs = (int*)(sm + 26368); // 64   -> total 26432 floats = 105728 B

  int tid = threadIdx.x, ty = tid >> 4, tx = tid & 15;
  int e0 = blockIdx.x * 64;

  if (tid < 64) {
    idxs[tid] = eidx[e0 + tid];
    float4 av = *(const float4*)(ea + (size_t)(e0 + tid)*4);
    a0s[tid] = av.x;
    a1s[tid*3 + 0] = av.y; a1s[tid*3 + 1] = av.z; a1s[tid*3 + 2] = av.w;
  }
  __syncthreads();

  // gather s0 + s1 planes; first weight tile concurrently
  for (int f = tid; f < 4096; f += 256) {
    int e = f >> 6, c4 = f & 63;
    float4 v = *(const float4*)(g_x + (size_t)idxs[e]*256 + c4*4);
    if (c4 < 16) *(float4*)(S0 + e*PAD + c4*4) = v;
    else {
      int m = (c4 - 16) >> 4, cc = (c4 - 16) & 15;
      *(float4*)(S1 + m*4352 + e*PAD + cc*4) = v;
    }
  }
  load_w64(Wb, g_wt + WT_L1A, tid);
  __syncthreads();

  const float* tp0 = g_tp + (size_t)e0 * 64;
  const size_t QS = (size_t)NEDGES * 64;

  float U[4][4], Y[4][4], acc[4][4];

  // q=1 : Tb = w2 ∘ S0 ; U = Tb @ L1A
  for (int f = tid; f < 1024; f += 256) {
    int e = f >> 4, c4 = f & 15;
    float4 w = *(const float4*)(tp0 + 1*QS + e*64 + c4*4);
    float4 s = *(const float4*)(S0 + e*PAD + c4*4);
    float4 r; r.x = w.x*s.x; r.y = w.y*s.y; r.z = w.z*s.z; r.w = w.w*s.w;
    *(float4*)(Tb + e*PAD + c4*4) = r;
  }
  __syncthreads();
#pragma unroll
  for (int i = 0; i < 4; i++)
#pragma unroll
    for (int j = 0; j < 4; j++) U[i][j] = 0.f;
  gemm4x4<64, PAD>(Tb, Wb, U, ty, tx);
  __syncthreads();

  // q=0 : Tb = w1 ∘ S0 ∘ a0 ; Y = Tb @ L0A
  load_w64(Wb, g_wt + WT_L0A, tid);
  for (int f = tid; f < 1024; f += 256) {
    int e = f >> 4, c4 = f & 15;
    float4 w = *(const float4*)(tp0 + e*64 + c4*4);
    float4 s = *(const float4*)(S0 + e*PAD + c4*4);
    float az = a0s[e];
    float4 r; r.x = w.x*s.x*az; r.y = w.y*s.y*az; r.z = w.z*s.z*az; r.w = w.w*s.w*az;
    *(float4*)(Tb + e*PAD + c4*4) = r;
  }
  __syncthreads();
#pragma unroll
  for (int i = 0; i < 4; i++)
#pragma unroll
    for (int j = 0; j < 4; j++) Y[i][j] = 0.f;
  gemm4x4<64, PAD>(Tb, Wb, Y, ty, tx);
  __syncthreads();

  // q=3 : Tb = w4 ∘ dot(S1,a1)/sqrt3 ; Y += Tb @ L0B
  load_w64(Wb, g_wt + WT_L0B, tid);
  for (int f = tid; f < 1024; f += 256) {
    int e = f >> 4, c4 = f & 15;
    float4 w = *(const float4*)(tp0 + 3*QS + e*64 + c4*4);
    float4 s0m = *(const float4*)(S1 + 0*4352 + e*PAD + c4*4);
    float4 s1m = *(const float4*)(S1 + 1*4352 + e*PAD + c4*4);
    float4 s2m = *(const float4*)(S1 + 2*4352 + e*PAD + c4*4);
    float a1x = a1s[e*3+0], a1y = a1s[e*3+1], a1z = a1s[e*3+2];
    float4 r;
    r.x = w.x * (s0m.x*a1x + s1m.x*a1y + s2m.x*a1z) * INV_SQRT3;
    r.y = w.y * (s0m.y*a1x + s1m.y*a1y + s2m.y*a1z) * INV_SQRT3;
    r.z = w.z * (s0m.z*a1x + s1m.z*a1y + s2m.z*a1z) * INV_SQRT3;
    r.w = w.w * (s0m.w*a1x + s1m.w*a1y + s2m.w*a1z) * INV_SQRT3;
    *(float4*)(Tb + e*PAD + c4*4) = r;
  }
  __syncthreads();
  gemm4x4<64, PAD>(Tb, Wb, Y, ty, tx);
  __syncthreads();

  // stash Y into S0 region (S0 data dead); load L1B
#pragma unroll
  for (int i = 0; i < 4; i++) {
    int e = ty*4 + i;
#pragma unroll
    for (int j = 0; j < 4; j++) S0[e*PAD + tx + 16*j] = Y[i][j];
  }
  load_w64(Wb, g_wt + WT_L1B, tid);

  // q=2 per m : Tb = w3 ∘ S1_m ; V = Tb @ L1B ; y1_m -> S1_m region
#pragma unroll
  for (int m = 0; m < 3; m++) {
    for (int f = tid; f < 1024; f += 256) {
      int e = f >> 4, c4 = f & 15;
      float4 w = *(const float4*)(tp0 + 2*QS + e*64 + c4*4);
      float4 s = *(const float4*)(S1 + m*4352 + e*PAD + c4*4);
      float4 r; r.x = w.x*s.x; r.y = w.y*s.y; r.z = w.z*s.z; r.w = w.w*s.w;
      *(float4*)(Tb + e*PAD + c4*4) = r;
    }
    __syncthreads();
#pragma unroll
    for (int i = 0; i < 4; i++)
#pragma unroll
      for (int j = 0; j < 4; j++) acc[i][j] = 0.f;
    gemm4x4<64, PAD>(Tb, Wb, acc, ty, tx);
#pragma unroll
    for (int i = 0; i < 4; i++) {
      int e = ty*4 + i;
      float am = a1s[e*3 + m], az = a0s[e];
#pragma unroll
      for (int j = 0; j < 4; j++)
        S1[m*4352 + e*PAD + tx + 16*j] = am*U[i][j] + az*acc[i][j];
    }
    __syncthreads();
  }

  // coalesced writeout: out[e][col] ; col<64 from S0 region, else plane m=t%3, d=t/3
  float* og = out + (size_t)e0 * 256;
  for (int f = tid; f < 4096; f += 256) {
    int e = f >> 6, c4 = f & 63;
    float4 r;
    float vv[4];
#pragma unroll
    for (int k = 0; k < 4; k++) {
      int col = c4*4 + k;
      if (col < 64) vv[k] = S0[e*PAD + col];
      else {
        int t = col - 64;
        int d = t / 3, m = t - d*3;
        vv[k] = S1[m*4352 + e*PAD + d];
      }
    }
    r.x = vv[0]; r.y = vv[1]; r.z = vv[2]; r.w = vv[3];
    *(float4*)(og + f*4) = r;
  }
}

extern "C" void kernel_launch(void* const* d_in, const int* in_sizes, int n_in,
                              void* d_out, int out_size) {
  (void)in_sizes; (void)n_in; (void)out_size;
  const float* nf  = (const float*)d_in[0];
  const float* ea  = (const float*)d_in[1];
  const float* ef  = (const float*)d_in[2];
  const float* up0 = (const float*)d_in[3];
  const float* up1 = (const float*)d_in[4];
  const float* w1  = (const float*)d_in[5];
  const float* w2  = (const float*)d_in[6];
  const float* w3  = (const float*)d_in[7];
  const float* w4  = (const float*)d_in[8];
  const float* l0  = (const float*)d_in[9];
  const float* l1  = (const float*)d_in[10];
  const int*  eidx = (const int*)d_in[11];
  float* out = (float*)d_out;

  cudaFuncSetAttribute(node_kernel,  cudaFuncAttributeMaxDynamicSharedMemorySize, 100352);
  cudaFuncSetAttribute(mlp_kernel,   cudaFuncAttributeMaxDynamicSharedMemorySize, 91136);
  cudaFuncSetAttribute(edge2_kernel, cudaFuncAttributeMaxDynamicSharedMemorySize, 105728);

  prep_kernel<<<(49664 + 255) / 256, 256>>>(w1, w2, w3, w4, l0, l1, up0, up1);
  node_kernel<<<(NNODES + 63) / 64, 256, 100352>>>(nf);
  mlp_kernel<<<NEDGES / 128, 256, 91136>>>(ef);
  edge2_kernel<<<NEDGES / 64, 256, 105728>>>(ea, eidx, out);
}

// round 6
// speedup vs baseline: 1.7017x; 1.0112x over previous
#include <cuda_runtime.h>

#define NNODES 50000
#define NEDGES 400000
#define PAD 68
#define INV_SQRT3 0.57735026918962576451f

__device__ float g_x[(size_t)NNODES * 256];
__device__ float g_tp[(size_t)4 * NEDGES * 64];
__device__ float g_wt[49664];

#define WT_MLP1 0
#define WT_MLP2 512
#define WT_MLP3 4608
#define WT_MLP4 8704
#define WT_L0A  25088
#define WT_L0B  29184
#define WT_L1A  33280
#define WT_L1B  37376
#define WT_UP0  41472
#define WT_UP1  45568

__global__ void prep_kernel(const float* __restrict__ w1, const float* __restrict__ w2,
                            const float* __restrict__ w3, const float* __restrict__ w4,
                            const float* __restrict__ l0, const float* __restrict__ l1,
                            const float* __restrict__ up0, const float* __restrict__ up1) {
  int t = blockIdx.x * blockDim.x + threadIdx.x;
  if (t >= 49664) return;
  float v;
  if (t < 512)        { int u = t;        int n = u >> 3, k = u & 7;  v = w1[k*64 + n]; }
  else if (t < 4608)  { int u = t-512;    int n = u >> 6, k = u & 63; v = w2[k*64 + n]; }
  else if (t < 8704)  { int u = t-4608;   int n = u >> 6, k = u & 63; v = w3[k*64 + n]; }
  else if (t < 25088) { int u = t-8704;   int q = u >> 12; int r = u & 4095;
                        int n = r >> 6, k = r & 63;        v = w4[k*256 + q*64 + n]; }
  else if (t < 29184) { int u = t-25088;  int n = u >> 6, k = u & 63; v = l0[k*64 + n]; }
  else if (t < 33280) { int u = t-29184;  int n = u >> 6, k = u & 63; v = l0[(64+k)*64 + n]; }
  else if (t < 37376) { int u = t-33280;  int n = u >> 6, k = u & 63; v = l1[k*64 + n]; }
  else if (t < 41472) { int u = t-37376;  int n = u >> 6, k = u & 63; v = l1[(64+k)*64 + n]; }
  else if (t < 45568) { int u = t-41472;  int n = u >> 6, k = u & 63; v = up0[k*64 + n]; }
  else                { int u = t-45568;  int n = u >> 6, k = u & 63; v = up1[k*64 + n]; }
  g_wt[t] = v;
}

// 4 rows x 4 cols; rows = ty*4+i, cols = tx+16j; A stride LDA, B stride PAD
template<int K, int LDA>
__device__ __forceinline__ void gemm4x4(const float* __restrict__ A, const float* __restrict__ B,
                                        float acc[4][4], int ty, int tx) {
#pragma unroll
  for (int kk = 0; kk < K; kk += 4) {
    float4 b[4];
#pragma unroll
    for (int j = 0; j < 4; j++) b[j] = *(const float4*)(B + (tx + 16*j)*PAD + kk);
#pragma unroll
    for (int i = 0; i < 4; i++) {
      float4 a = *(const float4*)(A + (ty*4 + i)*LDA + kk);
#pragma unroll
      for (int j = 0; j < 4; j++) {
        float s = acc[i][j];
        s = fmaf(a.x, b[j].x, s);
        s = fmaf(a.y, b[j].y, s);
        s = fmaf(a.z, b[j].z, s);
        s = fmaf(a.w, b[j].w, s);
        acc[i][j] = s;
      }
    }
  }
}

// 8 rows x 4 cols; rows = ty*8+i
template<int K, int LDA>
__device__ __forceinline__ void gemm8x4(const float* __restrict__ A, const float* __restrict__ B,
                                        float acc[8][4], int ty, int tx) {
#pragma unroll
  for (int kk = 0; kk < K; kk += 4) {
    float4 b[4];
#pragma unroll
    for (int j = 0; j < 4; j++) b[j] = *(const float4*)(B + (tx + 16*j)*PAD + kk);
#pragma unroll
    for (int i = 0; i < 8; i++) {
      float4 a = *(const float4*)(A + (ty*8 + i)*LDA + kk);
#pragma unroll
      for (int j = 0; j < 4; j++) {
        float s = acc[i][j];
        s = fmaf(a.x, b[j].x, s);
        s = fmaf(a.y, b[j].y, s);
        s = fmaf(a.z, b[j].z, s);
        s = fmaf(a.w, b[j].w, s);
        acc[i][j] = s;
      }
    }
  }
}

__device__ __forceinline__ float silu_f(float x) { return x * (1.f / (1.f + __expf(-x))); }

__device__ __forceinline__ void load_w64(float* dst, const float* __restrict__ src, int tid) {
  for (int f = tid; f < 1024; f += 256) {
    int r = f >> 4, c = f & 15;
    *(float4*)(dst + r*PAD + c*4) = *(const float4*)(src + r*64 + c*4);
  }
}

// ---------------- node up-projection ----------------
__global__ __launch_bounds__(256) void node_kernel(const float* __restrict__ nf) {
  extern __shared__ float sm[];
  float* NF = sm;                  // 64 x 256
  float* Wt = sm + 16384;          // 64 x PAD
  float* Ab = sm + 16384 + 4352;   // 64 x PAD
  int tid = threadIdx.x, ty = tid >> 4, tx = tid & 15;
  int n0 = blockIdx.x * 64;

  for (int f = tid; f < 4096; f += 256) {
    int r = f >> 6, c4 = f & 63;
    if (n0 + r < NNODES)
      *(float4*)(NF + r*256 + c4*4) = *(const float4*)(nf + (size_t)(n0 + r)*256 + c4*4);
  }
  __syncthreads();

  for (int p = 0; p < 4; p++) {
    load_w64(Wt, g_wt + (p == 0 ? WT_UP0 : WT_UP1), tid);
    for (int f = tid; f < 4096; f += 256) {
      int r = f >> 6, c = f & 63;
      Ab[r*PAD + c] = (p == 0) ? NF[r*256 + c] : NF[r*256 + 64 + c*3 + (p - 1)];
    }
    __syncthreads();
    float fr[4][4];
#pragma unroll
    for (int i = 0; i < 4; i++)
#pragma unroll
      for (int j = 0; j < 4; j++) fr[i][j] = 0.f;
    gemm4x4<64, PAD>(Ab, Wt, fr, ty, tx);
#pragma unroll
    for (int i = 0; i < 4; i++) {
      int r = ty*4 + i;
      if (n0 + r < NNODES) {
#pragma unroll
        for (int j = 0; j < 4; j++)
          g_x[(size_t)(n0 + r)*256 + p*64 + tx + 16*j] = fr[i][j];
      }
    }
    __syncthreads();
  }
}

// ---------------- per-edge MLP -> g_tp (q-major), 128-edge tiles ----------------
__global__ __launch_bounds__(256, 2) void mlp_kernel(const float* __restrict__ ef) {
  extern __shared__ float sm[];
  float* F  = sm;           // 128 x 8   (1024)
  float* Wa = sm + 1024;    // 64 x PAD  (4352)
  float* A0 = sm + 5376;    // 128 x PAD (8704)
  float* A1 = sm + 14080;   // 128 x PAD (8704)  -> total 22784 floats
  int tid = threadIdx.x, ty = tid >> 4, tx = tid & 15;
  int e0 = blockIdx.x * 128;

  *(float4*)(F + tid*4) = *(const float4*)(ef + (size_t)e0*8 + tid*4);
  for (int f = tid; f < 128; f += 256) {
    int r = f >> 1, c = f & 1;
    *(float4*)(Wa + r*PAD + c*4) = *(const float4*)(g_wt + WT_MLP1 + r*8 + c*4);
  }
  __syncthreads();

  float fr[8][4];
#pragma unroll
  for (int i = 0; i < 8; i++)
#pragma unroll
    for (int j = 0; j < 4; j++) fr[i][j] = 0.f;
  gemm8x4<8, 8>(F, Wa, fr, ty, tx);
  __syncthreads();
#pragma unroll
  for (int i = 0; i < 8; i++) { int e = ty*8 + i;
#pragma unroll
    for (int j = 0; j < 4; j++) A0[e*PAD + tx + 16*j] = silu_f(fr[i][j]); }
  load_w64(Wa, g_wt + WT_MLP2, tid);
  __syncthreads();

#pragma unroll
  for (int i = 0; i < 8; i++)
#pragma unroll
    for (int j = 0; j < 4; j++) fr[i][j] = 0.f;
  gemm8x4<64, PAD>(A0, Wa, fr, ty, tx);
  __syncthreads();
#pragma unroll
  for (int i = 0; i < 8; i++) { int e = ty*8 + i;
#pragma unroll
    for (int j = 0; j < 4; j++) A1[e*PAD + tx + 16*j] = silu_f(fr[i][j]); }
  load_w64(Wa, g_wt + WT_MLP3, tid);
  __syncthreads();

#pragma unroll
  for (int i = 0; i < 8; i++)
#pragma unroll
    for (int j = 0; j < 4; j++) fr[i][j] = 0.f;
  gemm8x4<64, PAD>(A1, Wa, fr, ty, tx);
  __syncthreads();
#pragma unroll
  for (int i = 0; i < 8; i++) { int e = ty*8 + i;
#pragma unroll
    for (int j = 0; j < 4; j++) A0[e*PAD + tx + 16*j] = silu_f(fr[i][j]); }
  __syncthreads();

#pragma unroll
  for (int q = 0; q < 4; q++) {
    load_w64(Wa, g_wt + WT_MLP4 + q*4096, tid);
    __syncthreads();
#pragma unroll
    for (int i = 0; i < 8; i++)
#pragma unroll
      for (int j = 0; j < 4; j++) fr[i][j] = 0.f;
    gemm8x4<64, PAD>(A0, Wa, fr, ty, tx);
    float* og = g_tp + (size_t)q * NEDGES * 64 + (size_t)e0 * 64;
#pragma unroll
    for (int i = 0; i < 8; i++) { int e = ty*8 + i;
#pragma unroll
      for (int j = 0; j < 4; j++) og[e*64 + tx + 16*j] = fr[i][j]; }
    __syncthreads();
  }
}

// ---------------- tensor-product + final linears, 64-edge tiles ----------------
__global__ __launch_bounds__(256, 2) void edge2_kernel(const float* __restrict__ ea,
                                                       const int* __restrict__ eidx,
                                                       float* __restrict__ out) {
  extern __shared__ float sm[];
  float* S0  = sm;              // 4352   (later holds y0)
  float* S1  = sm + 4352;       // 3 x 4352 (later holds y1 planes)
  float* Tb  = sm + 17408;      // 4352
  float* Wb  = sm + 21760;      // 4352
  float* a0s = sm + 26112;      // 64
  float* a1s = sm + 26176;      // 192
  int*  idxs = (int*)(sm + 26368); // 64   -> total 26432 floats = 105728 B

  int tid = threadIdx.x, ty = tid >> 4, tx = tid & 15;
  int e0 = blockIdx.x * 64;

  if (tid < 64) {
    idxs[tid] = eidx[e0 + tid];
    float4 av = *(const float4*)(ea + (size_t)(e0 + tid)*4);
    a0s[tid] = av.x;
    a1s[tid*3 + 0] = av.y; a1s[tid*3 + 1] = av.z; a1s[tid*3 + 2] = av.w;
  }
  __syncthreads();

  // gather s0 + s1 planes; first weight tile concurrently
  for (int f = tid; f < 4096; f += 256) {
    int e = f >> 6, c4 = f & 63;
    float4 v = *(const float4*)(g_x + (size_t)idxs[e]*256 + c4*4);
    if (c4 < 16) *(float4*)(S0 + e*PAD + c4*4) = v;
    else {
      int m = (c4 - 16) >> 4, cc = (c4 - 16) & 15;
      *(float4*)(S1 + m*4352 + e*PAD + cc*4) = v;
    }
  }
  load_w64(Wb, g_wt + WT_L1A, tid);
  __syncthreads();

  const float* tp0 = g_tp + (size_t)e0 * 64;
  const size_t QS = (size_t)NEDGES * 64;

  float U[4][4], Y[4][4], acc[4][4];

  // q=1 : Tb = w2 ∘ S0 ; U = Tb @ L1A
  for (int f = tid; f < 1024; f += 256) {
    int e = f >> 4, c4 = f & 15;
    float4 w = *(const float4*)(tp0 + 1*QS + e*64 + c4*4);
    float4 s = *(const float4*)(S0 + e*PAD + c4*4);
    float4 r; r.x = w.x*s.x; r.y = w.y*s.y; r.z = w.z*s.z; r.w = w.w*s.w;
    *(float4*)(Tb + e*PAD + c4*4) = r;
  }
  __syncthreads();
#pragma unroll
  for (int i = 0; i < 4; i++)
#pragma unroll
    for (int j = 0; j < 4; j++) U[i][j] = 0.f;
  gemm4x4<64, PAD>(Tb, Wb, U, ty, tx);
  __syncthreads();

  // q=0 : Tb = w1 ∘ S0 ∘ a0 ; Y = Tb @ L0A
  load_w64(Wb, g_wt + WT_L0A, tid);
  for (int f = tid; f < 1024; f += 256) {
    int e = f >> 4, c4 = f & 15;
    float4 w = *(const float4*)(tp0 + e*64 + c4*4);
    float4 s = *(const float4*)(S0 + e*PAD + c4*4);
    float az = a0s[e];
    float4 r; r.x = w.x*s.x*az; r.y = w.y*s.y*az; r.z = w.z*s.z*az; r.w = w.w*s.w*az;
    *(float4*)(Tb + e*PAD + c4*4) = r;
  }
  __syncthreads();
#pragma unroll
  for (int i = 0; i < 4; i++)
#pragma unroll
    for (int j = 0; j < 4; j++) Y[i][j] = 0.f;
  gemm4x4<64, PAD>(Tb, Wb, Y, ty, tx);
  __syncthreads();

  // q=3 : Tb = w4 ∘ dot(S1,a1)/sqrt3 ; Y += Tb @ L0B
  load_w64(Wb, g_wt + WT_L0B, tid);
  for (int f = tid; f < 1024; f += 256) {
    int e = f >> 4, c4 = f & 15;
    float4 w = *(const float4*)(tp0 + 3*QS + e*64 + c4*4);
    float4 s0m = *(const float4*)(S1 + 0*4352 + e*PAD + c4*4);
    float4 s1m = *(const float4*)(S1 + 1*4352 + e*PAD + c4*4);
    float4 s2m = *(const float4*)(S1 + 2*4352 + e*PAD + c4*4);
    float a1x = a1s[e*3+0], a1y = a1s[e*3+1], a1z = a1s[e*3+2];
    float4 r;
    r.x = w.x * (s0m.x*a1x + s1m.x*a1y + s2m.x*a1z) * INV_SQRT3;
    r.y = w.y * (s0m.y*a1x + s1m.y*a1y + s2m.y*a1z) * INV_SQRT3;
    r.z = w.z * (s0m.z*a1x + s1m.z*a1y + s2m.z*a1z) * INV_SQRT3;
    r.w = w.w * (s0m.w*a1x + s1m.w*a1y + s2m.w*a1z) * INV_SQRT3;
    *(float4*)(Tb + e*PAD + c4*4) = r;
  }
  __syncthreads();
  gemm4x4<64, PAD>(Tb, Wb, Y, ty, tx);
  __syncthreads();

  // stash Y into S0 region (S0 data dead); load L1B
#pragma unroll
  for (int i = 0; i < 4; i++) {
    int e = ty*4 + i;
#pragma unroll
    for (int j = 0; j < 4; j++) S0[e*PAD + tx + 16*j] = Y[i][j];
  }
  load_w64(Wb, g_wt + WT_L1B, tid);

  // q=2 per m : Tb = w3 ∘ S1_m ; V = Tb @ L1B ; y1_m -> S1_m region
#pragma unroll
  for (int m = 0; m < 3; m++) {
    for (int f = tid; f < 1024; f += 256) {
      int e = f >> 4, c4 = f & 15;
      float4 w = *(const float4*)(tp0 + 2*QS + e*64 + c4*4);
      float4 s = *(const float4*)(S1 + m*4352 + e*PAD + c4*4);
      float4 r; r.x = w.x*s.x; r.y = w.y*s.y; r.z = w.z*s.z; r.w = w.w*s.w;
      *(float4*)(Tb + e*PAD + c4*4) = r;
    }
    __syncthreads();
#pragma unroll
    for (int i = 0; i < 4; i++)
#pragma unroll
      for (int j = 0; j < 4; j++) acc[i][j] = 0.f;
    gemm4x4<64, PAD>(Tb, Wb, acc, ty, tx);
#pragma unroll
    for (int i = 0; i < 4; i++) {
      int e = ty*4 + i;
      float am = a1s[e*3 + m], az = a0s[e];
#pragma unroll
      for (int j = 0; j < 4; j++)
        S1[m*4352 + e*PAD + tx + 16*j] = am*U[i][j] + az*acc[i][j];
    }
    __syncthreads();
  }

  // coalesced writeout: out[e][col] ; col<64 from S0 region, else plane m=t%3, d=t/3
  float* og = out + (size_t)e0 * 256;
  for (int f = tid; f < 4096; f += 256) {
    int e = f >> 6, c4 = f & 63;
    float4 r;
    float vv[4];
#pragma unroll
    for (int k = 0; k < 4; k++) {
      int col = c4*4 + k;
      if (col < 64) vv[k] = S0[e*PAD + col];
      else {
        int t = col - 64;
        int d = t / 3, m = t - d*3;
        vv[k] = S1[m*4352 + e*PAD + d];
      }
    }
    r.x = vv[0]; r.y = vv[1]; r.z = vv[2]; r.w = vv[3];
    *(float4*)(og + f*4) = r;
  }
}

extern "C" void kernel_launch(void* const* d_in, const int* in_sizes, int n_in,
                              void* d_out, int out_size) {
  (void)in_sizes; (void)n_in; (void)out_size;
  const float* nf  = (const float*)d_in[0];
  const float* ea  = (const float*)d_in[1];
  const float* ef  = (const float*)d_in[2];
  const float* up0 = (const float*)d_in[3];
  const float* up1 = (const float*)d_in[4];
  const float* w1  = (const float*)d_in[5];
  const float* w2  = (const float*)d_in[6];
  const float* w3  = (const float*)d_in[7];
  const float* w4  = (const float*)d_in[8];
  const float* l0  = (const float*)d_in[9];
  const float* l1  = (const float*)d_in[10];
  const int*  eidx = (const int*)d_in[11];
  float* out = (float*)d_out;

  cudaFuncSetAttribute(node_kernel,  cudaFuncAttributeMaxDynamicSharedMemorySize, 100352);
  cudaFuncSetAttribute(mlp_kernel,   cudaFuncAttributeMaxDynamicSharedMemorySize, 91136);
  cudaFuncSetAttribute(edge2_kernel, cudaFuncAttributeMaxDynamicSharedMemorySize, 105728);

  prep_kernel<<<(49664 + 255) / 256, 256>>>(w1, w2, w3, w4, l0, l1, up0, up1);
  node_kernel<<<(NNODES + 63) / 64, 256, 100352>>>(nf);
  mlp_kernel<<<NEDGES / 128, 256, 91136>>>(ef);
  edge2_kernel<<<NEDGES / 64, 256, 105728>>>(ea, eidx, out);
}